// round 7
// baseline (speedup 1.0000x reference)
#include <cuda_runtime.h>

#define BB 32
#define SS 8192
#define DD 256
#define KSEL 1638          // max(1, int(8192*0.2))
#define NCHUNK 32
#define ROWS_PER_CHUNK 256 // SS / NCHUNK
#define ROWS_PER_WARP 32
#define ECHUNK 32          // kB blocks per batch

// Scratch (no allocations allowed)
__device__ float g_w[BB * SS];                 // exp(tanh(x.W + b))
__device__ float g_Ppart[NCHUNK * BB * DD];    // per-chunk partial sum x*w (all rows)
__device__ float g_Epart[ECHUNK * BB * DD];    // per-chunk partial sum x*w (top-k rows)
__device__ float g_Psum[BB * DD];              // chunk-reduced P (computed in kA tail)
__device__ float g_invZ[BB];
__device__ int   g_idx[BB * SS];               // compacted accepted row indices
__device__ int   g_cntE[BB];                   // accepted count per batch
__device__ int   g_cnt1[BB];                   // arrival counters (self-resetting)
__device__ int   g_cnt2[BB];

// Branch-free w = exp(tanh(z)):  tanh(z) = 1 - 2/(e^{2z}+1)
__device__ __forceinline__ float exp_tanh(float z)
{
    const float ez = __expf(z + z);
    const float t  = 1.0f - __fdividef(2.0f, ez + 1.0f);
    return __expf(t);
}

// ---------------------------------------------------------------------------
// kA: dot, activation, P partials + per-batch last-block tail (k2 work).
// 8 warps/block, 32 rows/warp in groups of 4 rows with 8 lanes/row.
// W lives in shared memory (saves ~32 regs -> 3 blocks/SM).
// ---------------------------------------------------------------------------
__global__ __launch_bounds__(256, 3) void kA_kernel(const float* __restrict__ x,
                                                    const float* __restrict__ W,
                                                    const float* __restrict__ bias,
                                                    float* __restrict__ out_a)
{
    const int blk   = blockIdx.x;
    const int b     = blk / NCHUNK;
    const int chunk = blk % NCHUNK;
    const int warp  = threadIdx.x >> 5;
    const int lane  = threadIdx.x & 31;
    const int rowlocal = lane >> 3;   // 0..3
    const int e        = lane & 7;    // 0..7

    __shared__ float4 sW[64];
    if (threadIdx.x < 64) sW[threadIdx.x] = ((const float4*)W)[threadIdx.x];
    const float bv = bias[0];
    __syncthreads();

    float4 acc[8];
#pragma unroll
    for (int j = 0; j < 8; j++) acc[j] = make_float4(0.f, 0.f, 0.f, 0.f);

    const int s0 = chunk * ROWS_PER_CHUNK + warp * ROWS_PER_WARP;
    const float4* xb = (const float4*)(x + (size_t)b * SS * DD);

    for (int gi = 0; gi < 8; gi++) {
        const int srow = s0 + gi * 4 + rowlocal;
        const float4* xr = xb + (size_t)srow * (DD / 4);

        float4 v[8];
#pragma unroll
        for (int j = 0; j < 8; j++) v[j] = xr[j * 8 + e];   // d = j*32 + e*4

        float dp = 0.f;
#pragma unroll
        for (int j = 0; j < 8; j++) {
            const float4 wj = sW[j * 8 + e];
            dp += v[j].x * wj.x + v[j].y * wj.y + v[j].z * wj.z + v[j].w * wj.w;
        }

        dp += __shfl_xor_sync(0xffffffffu, dp, 1);
        dp += __shfl_xor_sync(0xffffffffu, dp, 2);
        dp += __shfl_xor_sync(0xffffffffu, dp, 4);

        const float wv = exp_tanh(dp + bv);
        if (e == 0) g_w[b * SS + srow] = wv;

#pragma unroll
        for (int j = 0; j < 8; j++) {
            acc[j].x += v[j].x * wv; acc[j].y += v[j].y * wv;
            acc[j].z += v[j].z * wv; acc[j].w += v[j].w * wv;
        }
    }

#pragma unroll
    for (int j = 0; j < 8; j++) {
        acc[j].x += __shfl_xor_sync(0xffffffffu, acc[j].x, 8);
        acc[j].y += __shfl_xor_sync(0xffffffffu, acc[j].y, 8);
        acc[j].z += __shfl_xor_sync(0xffffffffu, acc[j].z, 8);
        acc[j].w += __shfl_xor_sync(0xffffffffu, acc[j].w, 8);
        acc[j].x += __shfl_xor_sync(0xffffffffu, acc[j].x, 16);
        acc[j].y += __shfl_xor_sync(0xffffffffu, acc[j].y, 16);
        acc[j].z += __shfl_xor_sync(0xffffffffu, acc[j].z, 16);
        acc[j].w += __shfl_xor_sync(0xffffffffu, acc[j].w, 16);
    }

    __shared__ float4 sacc[8][64];   // [warp][d/4]
    if (lane < 8) {
#pragma unroll
        for (int j = 0; j < 8; j++) sacc[warp][j * 8 + e] = acc[j];
    }
    __syncthreads();

    {
        float tot = 0.f;
        const float* sflat = (const float*)sacc;
#pragma unroll
        for (int wp = 0; wp < 8; wp++) tot += sflat[wp * DD + threadIdx.x];
        g_Ppart[((size_t)chunk * BB + b) * DD + threadIdx.x] = tot;
    }

    // ---- last-block-per-batch gate ----
    __threadfence();
    __shared__ int slast;
    if (threadIdx.x == 0) {
        const int old = atomicAdd(&g_cnt1[b], 1);
        slast = (old == NCHUNK - 1);
        if (slast) g_cnt1[b] = 0;           // reset for next graph replay
    }
    __syncthreads();
    if (!slast) return;

    // =================== k2 tail for batch b ===================
    const int t = threadIdx.x;

    float wreg[32];
#pragma unroll
    for (int j = 0; j < 32; j++) wreg[j] = g_w[b * SS + j * 256 + t];

    __shared__ float sredf[8];
    __shared__ float sZ;
    __shared__ int   stot[32];
    if (t < 32) stot[t] = 0;

    // Z = sum(w)
    float z = 0.f;
#pragma unroll
    for (int j = 0; j < 32; j++) z += wreg[j];
#pragma unroll
    for (int off = 16; off; off >>= 1) z += __shfl_xor_sync(0xffffffffu, z, off);
    if (lane == 0) sredf[warp] = z;
    __syncthreads();
    if (t == 0) {
        float zz = 0.f;
        for (int i = 0; i < 8; i++) zz += sredf[i];
        sZ = zz;
    }

    // P chunk-reduction folded in (overlaps the barrier)
    {
        float p = 0.f;
#pragma unroll
        for (int c = 0; c < NCHUNK; c++)
            p += g_Ppart[((size_t)c * BB + b) * DD + t];
        g_Psum[b * DD + t] = p;
    }
    __syncthreads();
    const float invZ = 1.f / sZ;

    // exact KSEL-th largest via binary search on float bit patterns
    unsigned lo = 0x3E800000u;  // 0.25f
    unsigned hi = 0x40800000u;  // 4.0f
    int it = 0;
    while (hi - lo > 1u) {
        const unsigned mid = lo + ((hi - lo) >> 1);
        const float fm = __uint_as_float(mid);
        int c = 0;
#pragma unroll
        for (int j = 0; j < 32; j++) c += (wreg[j] >= fm);
        c = __reduce_add_sync(0xffffffffu, c);
        if (lane == 0) atomicAdd(&stot[it], c);
        __syncthreads();
        if (stot[it] >= KSEL) lo = mid; else hi = mid;
        it++;
    }
    const float thr = __uint_as_float(lo);
    if (t == 0) g_invZ[b] = invZ;

    // emphasized_a + accept mask
    unsigned accmask = 0u;
    int cnt = 0;
#pragma unroll
    for (int j = 0; j < 32; j++) {
        const float wv = wreg[j];
        const bool a = (wv >= thr);
        accmask |= (a ? 1u : 0u) << j;
        cnt += a ? 1 : 0;
        out_a[b * SS + j * 256 + t] = wv * invZ * (a ? 1.5f : 1.0f);
    }

    // deterministic ordered compaction of accepted indices
    int v = cnt;
#pragma unroll
    for (int off = 1; off < 32; off <<= 1) {
        const int n = __shfl_up_sync(0xffffffffu, v, off);
        if (lane >= off) v += n;
    }
    __shared__ int swsum[8];
    __shared__ int swbase[8];
    if (lane == 31) swsum[warp] = v;
    __syncthreads();
    if (t == 0) {
        int s = 0;
        for (int i = 0; i < 8; i++) { swbase[i] = s; s += swsum[i]; }
        g_cntE[b] = s;
    }
    __syncthreads();
    int base = swbase[warp] + v - cnt;   // exclusive prefix for this thread
    int* dst = g_idx + b * SS;
#pragma unroll
    for (int j = 0; j < 32; j++) {
        if ((accmask >> j) & 1u) dst[base++] = j * 256 + t;
    }
}

// ---------------------------------------------------------------------------
// kB: dense gather over compacted index list + per-batch last-block tail.
// Grid: BB*ECHUNK = 1024 blocks x 256 threads. Global warp g = chunk*8+warp
// (0..255) handles slots g, g+256, ... of ~1638 accepted rows.
// ---------------------------------------------------------------------------
__global__ __launch_bounds__(256) void kB_kernel(const float* __restrict__ x,
                                                 float* __restrict__ out_sum)
{
    const int b     = blockIdx.x / ECHUNK;
    const int chunk = blockIdx.x % ECHUNK;
    const int warp  = threadIdx.x >> 5;
    const int lane  = threadIdx.x & 31;
    const int g     = chunk * 8 + warp;   // 0..255

    const int cnt = g_cntE[b];
    const int*   idx  = g_idx + b * SS;
    const float* wrow = g_w + b * SS;
    const float4* xb  = (const float4*)(x + (size_t)b * SS * DD);

    float acc[8];
#pragma unroll
    for (int j = 0; j < 8; j++) acc[j] = 0.f;

    int s = g;
    for (; s + 256 < cnt; s += 512) {
        const int r0 = idx[s];
        const int r1 = idx[s + 256];
        const float w0 = wrow[r0];
        const float w1 = wrow[r1];
        const float4* x0 = xb + (size_t)r0 * (DD / 4);
        const float4* x1 = xb + (size_t)r1 * (DD / 4);
        float4 a0 = x0[lane], a1 = x0[32 + lane];
        float4 b0 = x1[lane], b1 = x1[32 + lane];
        acc[0] += a0.x * w0 + b0.x * w1; acc[1] += a0.y * w0 + b0.y * w1;
        acc[2] += a0.z * w0 + b0.z * w1; acc[3] += a0.w * w0 + b0.w * w1;
        acc[4] += a1.x * w0 + b1.x * w1; acc[5] += a1.y * w0 + b1.y * w1;
        acc[6] += a1.z * w0 + b1.z * w1; acc[7] += a1.w * w0 + b1.w * w1;
    }
    for (; s < cnt; s += 256) {
        const int r0 = idx[s];
        const float w0 = wrow[r0];
        const float4* x0 = xb + (size_t)r0 * (DD / 4);
        float4 a0 = x0[lane], a1 = x0[32 + lane];
        acc[0] += a0.x * w0; acc[1] += a0.y * w0;
        acc[2] += a0.z * w0; acc[3] += a0.w * w0;
        acc[4] += a1.x * w0; acc[5] += a1.y * w0;
        acc[6] += a1.z * w0; acc[7] += a1.w * w0;
    }

    __shared__ float sacc[8][DD];
#pragma unroll
    for (int j = 0; j < 4; j++) {
        sacc[warp][lane * 4 + j]       = acc[j];
        sacc[warp][128 + lane * 4 + j] = acc[4 + j];
    }
    __syncthreads();
    {
        float tot = 0.f;
#pragma unroll
        for (int wp = 0; wp < 8; wp++) tot += sacc[wp][threadIdx.x];
        g_Epart[((size_t)chunk * BB + b) * DD + threadIdx.x] = tot;
    }

    // ---- last-block-per-batch gate ----
    __threadfence();
    __shared__ int slast;
    if (threadIdx.x == 0) {
        const int old = atomicAdd(&g_cnt2[b], 1);
        slast = (old == ECHUNK - 1);
        if (slast) g_cnt2[b] = 0;
    }
    __syncthreads();
    if (!slast) return;

    // =================== final combine for batch b ===================
    const int t = threadIdx.x;
    float esum = 0.f;
#pragma unroll
    for (int c = 0; c < ECHUNK; c++)
        esum += g_Epart[((size_t)c * BB + b) * DD + t];
    out_sum[b * DD + t] = g_invZ[b] * (g_Psum[b * DD + t] + 0.5f * esum);
}

// ---------------------------------------------------------------------------
extern "C" void kernel_launch(void* const* d_in, const int* in_sizes, int n_in,
                              void* d_out, int out_size)
{
    const float* x    = (const float*)d_in[0];
    const float* W    = (const float*)d_in[1];
    const float* bias = (const float*)d_in[2];

    float* out      = (float*)d_out;
    float* out_sum  = out;              // [BB, DD]
    float* out_a    = out + BB * DD;    // [BB, SS]

    kA_kernel<<<BB * NCHUNK, 256>>>(x, W, bias, out_a);
    kB_kernel<<<BB * ECHUNK, 256>>>(x, out_sum);
}

// round 9
// speedup vs baseline: 1.2727x; 1.2727x over previous
#include <cuda_runtime.h>

#define BB 32
#define SS 8192
#define DD 256
#define KSEL 1638          // max(1, int(8192*0.2))
#define NCHUNK 32
#define ROWS_PER_CHUNK 256 // SS / NCHUNK
#define ROWS_PER_WARP 32
#define ECHUNK 32          // kB blocks per batch

// Scratch (no allocations allowed)
__device__ float g_w[BB * SS];                 // exp(tanh(x.W + b))
__device__ float g_Ppart[NCHUNK * BB * DD];    // per-chunk partial sum x*w (all rows)
__device__ float g_Epart[ECHUNK * BB * DD];    // per-chunk partial sum x*w (top-k rows)
__device__ float g_Psum[BB * DD];              // chunk-reduced P (computed in kA tail)
__device__ float g_invZ[BB];
__device__ int   g_idx[BB * SS];               // compacted accepted row indices
__device__ int   g_cntE[BB];                   // accepted count per batch
__device__ int   g_cnt1[BB];                   // arrival counters (self-resetting)
__device__ int   g_cnt2[BB];

// Branch-free w = exp(tanh(z)):  tanh(z) = 1 - 2/(e^{2z}+1)
__device__ __forceinline__ float exp_tanh(float z)
{
    const float ez = __expf(z + z);
    const float t  = 1.0f - __fdividef(2.0f, ez + 1.0f);
    return __expf(t);
}

// ---------------------------------------------------------------------------
// kA: dot, activation, P partials + per-batch last-block tail (k2 work).
// 8 warps/block, 32 rows/warp in groups of 4 rows with 8 lanes/row.
// W in smem; v double-buffered so next group's loads overlap current compute.
// ---------------------------------------------------------------------------
__global__ __launch_bounds__(256, 2) void kA_kernel(const float* __restrict__ x,
                                                    const float* __restrict__ W,
                                                    const float* __restrict__ bias,
                                                    float* __restrict__ out_a)
{
    const int blk   = blockIdx.x;
    const int b     = blk / NCHUNK;
    const int chunk = blk % NCHUNK;
    const int warp  = threadIdx.x >> 5;
    const int lane  = threadIdx.x & 31;
    const int rowlocal = lane >> 3;   // 0..3
    const int e        = lane & 7;    // 0..7

    __shared__ float4 sW[64];
    if (threadIdx.x < 64) sW[threadIdx.x] = ((const float4*)W)[threadIdx.x];
    const float bv = bias[0];
    __syncthreads();

    float4 acc[8];
#pragma unroll
    for (int j = 0; j < 8; j++) acc[j] = make_float4(0.f, 0.f, 0.f, 0.f);

    const int s0 = chunk * ROWS_PER_CHUNK + warp * ROWS_PER_WARP;
    const float4* xb = (const float4*)(x + (size_t)b * SS * DD);

    float4 v[2][8];   // double buffer
    {
        const float4* xr = xb + (size_t)(s0 + rowlocal) * (DD / 4);
#pragma unroll
        for (int j = 0; j < 8; j++) v[0][j] = xr[j * 8 + e];
    }

#pragma unroll
    for (int gi = 0; gi < 8; gi++) {
        const int cur = gi & 1;
        if (gi < 7) {
            const float4* xr = xb + (size_t)(s0 + (gi + 1) * 4 + rowlocal) * (DD / 4);
#pragma unroll
            for (int j = 0; j < 8; j++) v[cur ^ 1][j] = xr[j * 8 + e];
        }

        float dp = 0.f;
#pragma unroll
        for (int j = 0; j < 8; j++) {
            const float4 wj = sW[j * 8 + e];
            dp += v[cur][j].x * wj.x + v[cur][j].y * wj.y
                + v[cur][j].z * wj.z + v[cur][j].w * wj.w;
        }

        dp += __shfl_xor_sync(0xffffffffu, dp, 1);
        dp += __shfl_xor_sync(0xffffffffu, dp, 2);
        dp += __shfl_xor_sync(0xffffffffu, dp, 4);

        const float wv = exp_tanh(dp + bv);
        const int srow = s0 + gi * 4 + rowlocal;
        if (e == 0) g_w[b * SS + srow] = wv;

#pragma unroll
        for (int j = 0; j < 8; j++) {
            acc[j].x += v[cur][j].x * wv; acc[j].y += v[cur][j].y * wv;
            acc[j].z += v[cur][j].z * wv; acc[j].w += v[cur][j].w * wv;
        }
    }

#pragma unroll
    for (int j = 0; j < 8; j++) {
        acc[j].x += __shfl_xor_sync(0xffffffffu, acc[j].x, 8);
        acc[j].y += __shfl_xor_sync(0xffffffffu, acc[j].y, 8);
        acc[j].z += __shfl_xor_sync(0xffffffffu, acc[j].z, 8);
        acc[j].w += __shfl_xor_sync(0xffffffffu, acc[j].w, 8);
        acc[j].x += __shfl_xor_sync(0xffffffffu, acc[j].x, 16);
        acc[j].y += __shfl_xor_sync(0xffffffffu, acc[j].y, 16);
        acc[j].z += __shfl_xor_sync(0xffffffffu, acc[j].z, 16);
        acc[j].w += __shfl_xor_sync(0xffffffffu, acc[j].w, 16);
    }

    __shared__ float4 sacc[8][64];   // [warp][d/4]
    if (lane < 8) {
#pragma unroll
        for (int j = 0; j < 8; j++) sacc[warp][j * 8 + e] = acc[j];
    }
    __syncthreads();

    {
        float tot = 0.f;
        const float* sflat = (const float*)sacc;
#pragma unroll
        for (int wp = 0; wp < 8; wp++) tot += sflat[wp * DD + threadIdx.x];
        g_Ppart[((size_t)chunk * BB + b) * DD + threadIdx.x] = tot;
    }

    // ---- last-block-per-batch gate ----
    __threadfence();
    __shared__ int slast;
    if (threadIdx.x == 0) {
        const int old = atomicAdd(&g_cnt1[b], 1);
        slast = (old == NCHUNK - 1);
        if (slast) g_cnt1[b] = 0;           // reset for next graph replay
    }
    __syncthreads();
    if (!slast) return;

    // =================== k2 tail for batch b ===================
    const int t = threadIdx.x;

    float wreg[32];
#pragma unroll
    for (int j = 0; j < 32; j++) wreg[j] = g_w[b * SS + j * 256 + t];

    __shared__ float sredf[8];
    __shared__ float sZ;
    __shared__ int   stot[32];
    if (t < 32) stot[t] = 0;

    // Z = sum(w)
    float z = 0.f;
#pragma unroll
    for (int j = 0; j < 32; j++) z += wreg[j];
#pragma unroll
    for (int off = 16; off; off >>= 1) z += __shfl_xor_sync(0xffffffffu, z, off);
    if (lane == 0) sredf[warp] = z;
    __syncthreads();
    if (t == 0) {
        float zz = 0.f;
        for (int i = 0; i < 8; i++) zz += sredf[i];
        sZ = zz;
    }

    // P chunk-reduction folded in (overlaps the barrier)
    {
        float p = 0.f;
#pragma unroll
        for (int c = 0; c < NCHUNK; c++)
            p += g_Ppart[((size_t)c * BB + b) * DD + t];
        g_Psum[b * DD + t] = p;
    }
    __syncthreads();
    const float invZ = 1.f / sZ;

    // exact KSEL-th largest via binary search on float bit patterns
    unsigned lo = 0x3E800000u;  // 0.25f
    unsigned hi = 0x40800000u;  // 4.0f
    int it = 0;
    while (hi - lo > 1u) {
        const unsigned mid = lo + ((hi - lo) >> 1);
        const float fm = __uint_as_float(mid);
        int c = 0;
#pragma unroll
        for (int j = 0; j < 32; j++) c += (wreg[j] >= fm);
        c = __reduce_add_sync(0xffffffffu, c);
        if (lane == 0) atomicAdd(&stot[it], c);
        __syncthreads();
        if (stot[it] >= KSEL) lo = mid; else hi = mid;
        it++;
    }
    const float thr = __uint_as_float(lo);
    if (t == 0) g_invZ[b] = invZ;

    // emphasized_a + accept mask
    unsigned accmask = 0u;
    int cnt = 0;
#pragma unroll
    for (int j = 0; j < 32; j++) {
        const float wv = wreg[j];
        const bool a = (wv >= thr);
        accmask |= (a ? 1u : 0u) << j;
        cnt += a ? 1 : 0;
        out_a[b * SS + j * 256 + t] = wv * invZ * (a ? 1.5f : 1.0f);
    }

    // deterministic ordered compaction of accepted indices
    int v2 = cnt;
#pragma unroll
    for (int off = 1; off < 32; off <<= 1) {
        const int n = __shfl_up_sync(0xffffffffu, v2, off);
        if (lane >= off) v2 += n;
    }
    __shared__ int swsum[8];
    __shared__ int swbase[8];
    if (lane == 31) swsum[warp] = v2;
    __syncthreads();
    if (t == 0) {
        int s = 0;
        for (int i = 0; i < 8; i++) { swbase[i] = s; s += swsum[i]; }
        g_cntE[b] = s;
    }
    __syncthreads();
    int base = swbase[warp] + v2 - cnt;   // exclusive prefix for this thread
    int* dst = g_idx + b * SS;
#pragma unroll
    for (int j = 0; j < 32; j++) {
        if ((accmask >> j) & 1u) dst[base++] = j * 256 + t;
    }
}

// ---------------------------------------------------------------------------
// kB: dense gather over compacted index list. (idx, w) for up to 8 slots are
// preloaded (independent broadcast loads) before the x gathers, so the row
// LDGs front-batch. Per-batch last-block tail does the final combine.
// Grid: BB*ECHUNK = 1024 blocks x 256 threads; warp g handles slots
// g, g+256, g+512, ...
// ---------------------------------------------------------------------------
__global__ __launch_bounds__(256) void kB_kernel(const float* __restrict__ x,
                                                 float* __restrict__ out_sum)
{
    const int b     = blockIdx.x / ECHUNK;
    const int chunk = blockIdx.x % ECHUNK;
    const int warp  = threadIdx.x >> 5;
    const int lane  = threadIdx.x & 31;
    const int g     = chunk * 8 + warp;   // 0..255

    const int cnt = g_cntE[b];
    const int*   idx  = g_idx + b * SS;
    const float* wrow = g_w + b * SS;
    const float4* xb  = (const float4*)(x + (size_t)b * SS * DD);

    float acc[8];
#pragma unroll
    for (int j = 0; j < 8; j++) acc[j] = 0.f;

    for (int sbase = g; sbase < cnt; sbase += 8 * 256) {
        // preload up to 8 (row, weight) pairs — independent broadcast loads
        int   rr[8];
        float ww[8];
#pragma unroll
        for (int k = 0; k < 8; k++) {
            const int s = sbase + k * 256;
            const bool vld = (s < cnt);
            const int r = vld ? idx[s] : -1;
            rr[k] = r;
            ww[k] = vld ? wrow[r] : 0.f;
        }
        // dense gathers: addresses all ready -> LDGs batch deeply
#pragma unroll
        for (int k = 0; k < 8; k++) {
            if (rr[k] >= 0) {   // warp-uniform
                const float4* x0 = xb + (size_t)rr[k] * (DD / 4);
                const float4 a0 = x0[lane];
                const float4 a1 = x0[32 + lane];
                const float w0 = ww[k];
                acc[0] += a0.x * w0; acc[1] += a0.y * w0;
                acc[2] += a0.z * w0; acc[3] += a0.w * w0;
                acc[4] += a1.x * w0; acc[5] += a1.y * w0;
                acc[6] += a1.z * w0; acc[7] += a1.w * w0;
            }
        }
    }

    __shared__ float sacc[8][DD];
#pragma unroll
    for (int j = 0; j < 4; j++) {
        sacc[warp][lane * 4 + j]       = acc[j];
        sacc[warp][128 + lane * 4 + j] = acc[4 + j];
    }
    __syncthreads();
    {
        float tot = 0.f;
#pragma unroll
        for (int wp = 0; wp < 8; wp++) tot += sacc[wp][threadIdx.x];
        g_Epart[((size_t)chunk * BB + b) * DD + threadIdx.x] = tot;
    }

    // ---- last-block-per-batch gate ----
    __threadfence();
    __shared__ int slast;
    if (threadIdx.x == 0) {
        const int old = atomicAdd(&g_cnt2[b], 1);
        slast = (old == ECHUNK - 1);
        if (slast) g_cnt2[b] = 0;
    }
    __syncthreads();
    if (!slast) return;

    // =================== final combine for batch b ===================
    const int t = threadIdx.x;
    float esum = 0.f;
#pragma unroll
    for (int c = 0; c < ECHUNK; c++)
        esum += g_Epart[((size_t)c * BB + b) * DD + t];
    out_sum[b * DD + t] = g_invZ[b] * (g_Psum[b * DD + t] + 0.5f * esum);
}

// ---------------------------------------------------------------------------
extern "C" void kernel_launch(void* const* d_in, const int* in_sizes, int n_in,
                              void* d_out, int out_size)
{
    const float* x    = (const float*)d_in[0];
    const float* W    = (const float*)d_in[1];
    const float* bias = (const float*)d_in[2];

    float* out      = (float*)d_out;
    float* out_sum  = out;              // [BB, DD]
    float* out_a    = out + BB * DD;    // [BB, SS]

    kA_kernel<<<BB * NCHUNK, 256>>>(x, W, bias, out_a);
    kB_kernel<<<BB * ECHUNK, 256>>>(x, out_sum);
}

// round 10
// speedup vs baseline: 1.3044x; 1.0250x over previous
#include <cuda_runtime.h>
#include <cstdint>

#define BB 32
#define SS 8192
#define DD 256
#define KSEL 1638          // max(1, int(8192*0.2))
#define NCHUNK 32
#define ROWS_PER_CHUNK 256 // SS / NCHUNK
#define TROWS 16           // rows per smem tile (16 KB)
#define NTILES 16          // ROWS_PER_CHUNK / TROWS
#define ECHUNK 8           // kB blocks per batch (single wave)

// Scratch (no allocations allowed)
__device__ float g_w[BB * SS];
__device__ float g_Ppart[NCHUNK * BB * DD];
__device__ float g_Epart[ECHUNK * BB * DD];
__device__ float g_Psum[BB * DD];
__device__ float g_invZ[BB];
__device__ int   g_idx[BB * SS];
__device__ int   g_cntE[BB];
__device__ int   g_cnt1[BB];
__device__ int   g_cnt2[BB];

// Branch-free w = exp(tanh(z)):  tanh(z) = 1 - 2/(e^{2z}+1)
__device__ __forceinline__ float exp_tanh(float z)
{
    const float ez = __expf(z + z);
    const float t  = 1.0f - __fdividef(2.0f, ez + 1.0f);
    return __expf(t);
}

__device__ __forceinline__ void cp16(uint32_t saddr, const void* gptr)
{
    asm volatile("cp.async.cg.shared.global [%0], [%1], 16;\n"
                 :: "r"(saddr), "l"(gptr));
}

// ---------------------------------------------------------------------------
// kA: cp.async-staged streaming pass.
// Block = 256 rows, 16 tiles of 16 rows, double-buffered smem.
// Per tile: warp w computes rows w*2, w*2+1 (full-warp dot, 2 interleaved
// shuffle chains). acc held in regs. Tail (last block per batch) = k2 work.
// ---------------------------------------------------------------------------
__global__ void kA_kernel(const float* __restrict__ x,
                          const float* __restrict__ W,
                          const float* __restrict__ bias,
                          float* __restrict__ out_a)
{
    __shared__ float4 sbuf[2][TROWS * 64];   // 2 x 16 KB
    __shared__ float  sacc[8][DD];           // 8 KB

    const int blk   = blockIdx.x;
    const int b     = blk / NCHUNK;
    const int chunk = blk % NCHUNK;
    const int tid   = threadIdx.x;
    const int warp  = tid >> 5;
    const int lane  = tid & 31;

    float w0[4], w1[4];
#pragma unroll
    for (int j = 0; j < 4; j++) {
        w0[j] = W[lane * 4 + j];
        w1[j] = W[128 + lane * 4 + j];
    }
    const float bv = bias[0];

    const int rowbase = chunk * ROWS_PER_CHUNK;
    const float4* xb = (const float4*)(x + (size_t)b * SS * DD);

    const uint32_t sb[2] = {
        (uint32_t)__cvta_generic_to_shared(&sbuf[0][0]),
        (uint32_t)__cvta_generic_to_shared(&sbuf[1][0])
    };

    // issue tile t into buffer t&1 (1024 float4 per tile, 4 per thread)
    #define ISSUE_TILE(t)                                                     \
    do {                                                                      \
        const float4* _src = xb + (size_t)(rowbase + (t) * TROWS) * 64;       \
        const uint32_t _dst = sb[(t) & 1];                                    \
        _Pragma("unroll")                                                     \
        for (int _k = 0; _k < 4; _k++)                                        \
            cp16(_dst + (uint32_t)(tid + 256 * _k) * 16u, _src + tid + 256 * _k); \
        asm volatile("cp.async.commit_group;\n" ::: "memory");                \
    } while (0)

    ISSUE_TILE(0);
    ISSUE_TILE(1);

    float acc[8];
#pragma unroll
    for (int j = 0; j < 8; j++) acc[j] = 0.f;

    for (int t = 0; t < NTILES; t++) {
        if (t < NTILES - 1) asm volatile("cp.async.wait_group 1;\n" ::: "memory");
        else                asm volatile("cp.async.wait_group 0;\n" ::: "memory");
        __syncthreads();

        const float4* sm = &sbuf[t & 1][0];

        float4 v0[2], v1[2];
        float dp[2];
#pragma unroll
        for (int r = 0; r < 2; r++) {
            const float4* row = sm + (warp * 2 + r) * 64;
            v0[r] = row[lane];
            v1[r] = row[32 + lane];
            dp[r] = v0[r].x * w0[0] + v0[r].y * w0[1] + v0[r].z * w0[2] + v0[r].w * w0[3]
                  + v1[r].x * w1[0] + v1[r].y * w1[1] + v1[r].z * w1[2] + v1[r].w * w1[3];
        }
#pragma unroll
        for (int off = 16; off; off >>= 1) {
            dp[0] += __shfl_xor_sync(0xffffffffu, dp[0], off);
            dp[1] += __shfl_xor_sync(0xffffffffu, dp[1], off);
        }
        float wv[2];
        wv[0] = exp_tanh(dp[0] + bv);
        wv[1] = exp_tanh(dp[1] + bv);

        const int srow = rowbase + t * TROWS + warp * 2;
        if (lane < 2) g_w[b * SS + srow + lane] = lane ? wv[1] : wv[0];

#pragma unroll
        for (int r = 0; r < 2; r++) {
            acc[0] += v0[r].x * wv[r]; acc[1] += v0[r].y * wv[r];
            acc[2] += v0[r].z * wv[r]; acc[3] += v0[r].w * wv[r];
            acc[4] += v1[r].x * wv[r]; acc[5] += v1[r].y * wv[r];
            acc[6] += v1[r].z * wv[r]; acc[7] += v1[r].w * wv[r];
        }

        __syncthreads();             // compute done before buffer reuse
        if (t + 2 < NTILES) ISSUE_TILE(t + 2);
    }
    #undef ISSUE_TILE

    // cross-warp combine
#pragma unroll
    for (int j = 0; j < 4; j++) {
        sacc[warp][lane * 4 + j]       = acc[j];
        sacc[warp][128 + lane * 4 + j] = acc[4 + j];
    }
    __syncthreads();
    {
        float tot = 0.f;
#pragma unroll
        for (int wp = 0; wp < 8; wp++) tot += sacc[wp][tid];
        g_Ppart[((size_t)chunk * BB + b) * DD + tid] = tot;
    }

    // ---- last-block-per-batch gate ----
    __threadfence();
    __shared__ int slast;
    if (tid == 0) {
        const int old = atomicAdd(&g_cnt1[b], 1);
        slast = (old == NCHUNK - 1);
        if (slast) g_cnt1[b] = 0;           // reset for next graph replay
    }
    __syncthreads();
    if (!slast) return;

    // =================== k2 tail for batch b ===================
    const int t = tid;

    float wreg[32];
#pragma unroll
    for (int j = 0; j < 32; j++) wreg[j] = g_w[b * SS + j * 256 + t];

    __shared__ float sredf[8];
    __shared__ float sZ;
    __shared__ int   stot[32];
    if (t < 32) stot[t] = 0;

    float z = 0.f;
#pragma unroll
    for (int j = 0; j < 32; j++) z += wreg[j];
#pragma unroll
    for (int off = 16; off; off >>= 1) z += __shfl_xor_sync(0xffffffffu, z, off);
    if (lane == 0) sredf[warp] = z;
    __syncthreads();
    if (t == 0) {
        float zz = 0.f;
        for (int i = 0; i < 8; i++) zz += sredf[i];
        sZ = zz;
    }

    // P chunk-reduction folded in
    {
        float p = 0.f;
#pragma unroll
        for (int c = 0; c < NCHUNK; c++)
            p += g_Ppart[((size_t)c * BB + b) * DD + t];
        g_Psum[b * DD + t] = p;
    }
    __syncthreads();
    const float invZ = 1.f / sZ;

    // exact KSEL-th largest via binary search on float bit patterns
    unsigned lo = 0x3E800000u;  // 0.25f
    unsigned hi = 0x40800000u;  // 4.0f
    int it = 0;
    while (hi - lo > 1u) {
        const unsigned mid = lo + ((hi - lo) >> 1);
        const float fm = __uint_as_float(mid);
        int c = 0;
#pragma unroll
        for (int j = 0; j < 32; j++) c += (wreg[j] >= fm);
        c = __reduce_add_sync(0xffffffffu, c);
        if (lane == 0) atomicAdd(&stot[it], c);
        __syncthreads();
        if (stot[it] >= KSEL) lo = mid; else hi = mid;
        it++;
    }
    const float thr = __uint_as_float(lo);
    if (t == 0) g_invZ[b] = invZ;

    unsigned accmask = 0u;
    int cnt = 0;
#pragma unroll
    for (int j = 0; j < 32; j++) {
        const float wv = wreg[j];
        const bool a = (wv >= thr);
        accmask |= (a ? 1u : 0u) << j;
        cnt += a ? 1 : 0;
        out_a[b * SS + j * 256 + t] = wv * invZ * (a ? 1.5f : 1.0f);
    }

    // deterministic ordered compaction of accepted indices
    int v2 = cnt;
#pragma unroll
    for (int off = 1; off < 32; off <<= 1) {
        const int n = __shfl_up_sync(0xffffffffu, v2, off);
        if (lane >= off) v2 += n;
    }
    __shared__ int swsum[8];
    __shared__ int swbase[8];
    if (lane == 31) swsum[warp] = v2;
    __syncthreads();
    if (t == 0) {
        int s = 0;
        for (int i = 0; i < 8; i++) { swbase[i] = s; s += swsum[i]; }
        g_cntE[b] = s;
    }
    __syncthreads();
    int base = swbase[warp] + v2 - cnt;
    int* dst = g_idx + b * SS;
#pragma unroll
    for (int j = 0; j < 32; j++) {
        if ((accmask >> j) & 1u) dst[base++] = j * 256 + t;
    }
}

// ---------------------------------------------------------------------------
// kB: dense gather over compacted index list. 256 blocks (single wave);
// warp g in 0..63 per batch handles slots g, g+64, ... (~25 rows) with
// 8-slot (idx,w) preload so row LDGs batch deeply. Tail = final combine.
// ---------------------------------------------------------------------------
__global__ __launch_bounds__(256) void kB_kernel(const float* __restrict__ x,
                                                 float* __restrict__ out_sum)
{
    const int b     = blockIdx.x / ECHUNK;
    const int chunk = blockIdx.x % ECHUNK;
    const int warp  = threadIdx.x >> 5;
    const int lane  = threadIdx.x & 31;
    const int g     = chunk * 8 + warp;   // 0..63

    const int cnt = g_cntE[b];
    const int*   idx  = g_idx + b * SS;
    const float* wrow = g_w + b * SS;
    const float4* xb  = (const float4*)(x + (size_t)b * SS * DD);

    float acc[8];
#pragma unroll
    for (int j = 0; j < 8; j++) acc[j] = 0.f;

    for (int sbase = g; sbase < cnt; sbase += 8 * 64) {
        int   rr[8];
        float ww[8];
#pragma unroll
        for (int k = 0; k < 8; k++) {
            const int s = sbase + k * 64;
            const bool vld = (s < cnt);
            const int r = vld ? idx[s] : -1;
            rr[k] = r;
            ww[k] = vld ? wrow[r] : 0.f;
        }
#pragma unroll
        for (int k = 0; k < 8; k++) {
            if (rr[k] >= 0) {   // warp-uniform
                const float4* x0 = xb + (size_t)rr[k] * (DD / 4);
                const float4 a0 = x0[lane];
                const float4 a1 = x0[32 + lane];
                const float w0 = ww[k];
                acc[0] += a0.x * w0; acc[1] += a0.y * w0;
                acc[2] += a0.z * w0; acc[3] += a0.w * w0;
                acc[4] += a1.x * w0; acc[5] += a1.y * w0;
                acc[6] += a1.z * w0; acc[7] += a1.w * w0;
            }
        }
    }

    __shared__ float sacc[8][DD];
#pragma unroll
    for (int j = 0; j < 4; j++) {
        sacc[warp][lane * 4 + j]       = acc[j];
        sacc[warp][128 + lane * 4 + j] = acc[4 + j];
    }
    __syncthreads();
    {
        float tot = 0.f;
#pragma unroll
        for (int wp = 0; wp < 8; wp++) tot += sacc[wp][threadIdx.x];
        g_Epart[((size_t)chunk * BB + b) * DD + threadIdx.x] = tot;
    }

    // ---- last-block-per-batch gate ----
    __threadfence();
    __shared__ int slast;
    if (threadIdx.x == 0) {
        const int old = atomicAdd(&g_cnt2[b], 1);
        slast = (old == ECHUNK - 1);
        if (slast) g_cnt2[b] = 0;
    }
    __syncthreads();
    if (!slast) return;

    // =================== final combine for batch b ===================
    const int t = threadIdx.x;
    float esum = 0.f;
#pragma unroll
    for (int c = 0; c < ECHUNK; c++)
        esum += g_Epart[((size_t)c * BB + b) * DD + t];
    out_sum[b * DD + t] = g_invZ[b] * (g_Psum[b * DD + t] + 0.5f * esum);
}

// ---------------------------------------------------------------------------
extern "C" void kernel_launch(void* const* d_in, const int* in_sizes, int n_in,
                              void* d_out, int out_size)
{
    const float* x    = (const float*)d_in[0];
    const float* W    = (const float*)d_in[1];
    const float* bias = (const float*)d_in[2];

    float* out      = (float*)d_out;
    float* out_sum  = out;              // [BB, DD]
    float* out_a    = out + BB * DD;    // [BB, SS]

    kA_kernel<<<BB * NCHUNK, 256>>>(x, W, bias, out_a);
    kB_kernel<<<BB * ECHUNK, 256>>>(x, out_sum);
}

// round 12
// speedup vs baseline: 1.3697x; 1.0500x over previous
#include <cuda_runtime.h>
#include <cstdint>

#define BB 32
#define SS 8192
#define DD 256
#define KSEL 1638          // max(1, int(8192*0.2))
#define NCHUNK 32
#define ROWS_PER_CHUNK 256 // SS / NCHUNK
#define TROWS 16           // rows per smem tile (16 KB)
#define NTILES 16          // ROWS_PER_CHUNK / TROWS
#define TILE_BYTES (TROWS * DD * 4)
#define KA_SMEM (3 * TILE_BYTES)   // 49152 dynamic
#define ECHUNK 16          // kB blocks per batch

// Scratch (no allocations allowed)
__device__ float g_w[BB * SS];
__device__ float g_Ppart[NCHUNK * BB * DD];
__device__ float g_Epart[ECHUNK * BB * DD];
__device__ float g_Psum[BB * DD];
__device__ float g_invZ[BB];
__device__ int   g_idx[BB * SS];
__device__ int   g_cntE[BB];
__device__ int   g_cnt1[BB];
__device__ int   g_cnt2[BB];

// Branch-free w = exp(tanh(z)):  tanh(z) = 1 - 2/(e^{2z}+1)
__device__ __forceinline__ float exp_tanh(float z)
{
    const float ez = __expf(z + z);
    const float t  = 1.0f - __fdividef(2.0f, ez + 1.0f);
    return __expf(t);
}

__device__ __forceinline__ void cp16(uint32_t saddr, const void* gptr)
{
    asm volatile("cp.async.cg.shared.global [%0], [%1], 16;\n"
                 :: "r"(saddr), "l"(gptr));
}

// ---------------------------------------------------------------------------
// kA: cp.async triple-buffered streaming pass (1 barrier per tile).
// Tile = 16 rows. Warp handles 2 rows: lane = (r, e), r = lane>>4, e = lane&15.
// Lane covers d = j*64 + e*4 (+0..3), j = 0..3. Row reduce = 4 shfl_xor.
// Tail (last block per batch) = softmax Z, exact top-k threshold, out_a,
// Psum, ordered index compaction.
// ---------------------------------------------------------------------------
__global__ __launch_bounds__(256) void kA_kernel(const float* __restrict__ x,
                                                 const float* __restrict__ W,
                                                 const float* __restrict__ bias,
                                                 float* __restrict__ out_a)
{
    extern __shared__ __align__(16) char smem_raw[];   // 3 x 16KB tiles / sacc

    const int blk   = blockIdx.x;
    const int b     = blk / NCHUNK;
    const int chunk = blk % NCHUNK;
    const int tid   = threadIdx.x;
    const int warp  = tid >> 5;
    const int lane  = tid & 31;
    const int r     = lane >> 4;    // 0..1 : row within warp pair
    const int e     = lane & 15;    // 0..15: 16 lanes per row

    // W slice: lane needs d = j*64 + e*4 .. +3
    const float4* Wf4 = (const float4*)W;
    float4 wv4[4];
#pragma unroll
    for (int j = 0; j < 4; j++) wv4[j] = Wf4[j * 16 + e];
    const float bv = bias[0];

    const int rowbase = chunk * ROWS_PER_CHUNK;
    const float4* xb = (const float4*)(x + (size_t)b * SS * DD);
    const uint32_t sb_base = (uint32_t)__cvta_generic_to_shared(smem_raw);

    #define ISSUE_TILE(t)                                                        \
    do {                                                                         \
        const float4* _src = xb + (size_t)(rowbase + (t) * TROWS) * 64;          \
        const uint32_t _dst = sb_base + (uint32_t)(((t) % 3) * TILE_BYTES);      \
        _Pragma("unroll")                                                        \
        for (int _k = 0; _k < 4; _k++)                                           \
            cp16(_dst + (uint32_t)(tid + 256 * _k) * 16u, _src + tid + 256 * _k);\
        asm volatile("cp.async.commit_group;\n" ::: "memory");                   \
    } while (0)

    ISSUE_TILE(0);
    ISSUE_TILE(1);

    float4 acc[4];
#pragma unroll
    for (int j = 0; j < 4; j++) acc[j] = make_float4(0.f, 0.f, 0.f, 0.f);

    for (int t = 0; t < NTILES; t++) {
        if (t < NTILES - 1) asm volatile("cp.async.wait_group 1;\n" ::: "memory");
        else                asm volatile("cp.async.wait_group 0;\n" ::: "memory");
        __syncthreads();   // all warps finished tile t-1 -> buf (t-1)%3 free

        if (t + 2 < NTILES) ISSUE_TILE(t + 2);   // goes into buf (t-1)%3

        const float4* sm  = (const float4*)(smem_raw + (t % 3) * TILE_BYTES);
        const float4* row = sm + (warp * 2 + r) * 64;

        float4 v[4];
#pragma unroll
        for (int j = 0; j < 4; j++) v[j] = row[j * 16 + e];

        float dp = 0.f;
#pragma unroll
        for (int j = 0; j < 4; j++)
            dp += v[j].x * wv4[j].x + v[j].y * wv4[j].y
                + v[j].z * wv4[j].z + v[j].w * wv4[j].w;

        dp += __shfl_xor_sync(0xffffffffu, dp, 1);
        dp += __shfl_xor_sync(0xffffffffu, dp, 2);
        dp += __shfl_xor_sync(0xffffffffu, dp, 4);
        dp += __shfl_xor_sync(0xffffffffu, dp, 8);

        const float wv = exp_tanh(dp + bv);
        const int srow = rowbase + t * TROWS + warp * 2 + r;
        if (e == 0) g_w[b * SS + srow] = wv;

#pragma unroll
        for (int j = 0; j < 4; j++) {
            acc[j].x += v[j].x * wv; acc[j].y += v[j].y * wv;
            acc[j].z += v[j].z * wv; acc[j].w += v[j].w * wv;
        }
    }
    #undef ISSUE_TILE

    // combine the two rows of each warp (lanes differing in bit 4)
#pragma unroll
    for (int j = 0; j < 4; j++) {
        acc[j].x += __shfl_xor_sync(0xffffffffu, acc[j].x, 16);
        acc[j].y += __shfl_xor_sync(0xffffffffu, acc[j].y, 16);
        acc[j].z += __shfl_xor_sync(0xffffffffu, acc[j].z, 16);
        acc[j].w += __shfl_xor_sync(0xffffffffu, acc[j].w, 16);
    }

    // cross-warp combine; reuse tile buffer 0 as sacc[8][256]
    __syncthreads();   // everyone done with tile buffers
    float* saccf = (float*)smem_raw;
    if (r == 0) {
        float4* sv = (float4*)smem_raw;
#pragma unroll
        for (int j = 0; j < 4; j++) sv[warp * 64 + j * 16 + e] = acc[j];
    }
    __syncthreads();
    {
        float tot = 0.f;
#pragma unroll
        for (int wp = 0; wp < 8; wp++) tot += saccf[wp * DD + tid];
        g_Ppart[((size_t)chunk * BB + b) * DD + tid] = tot;
    }

    // ---- last-block-per-batch gate ----
    __threadfence();
    __shared__ int slast;
    if (tid == 0) {
        const int old = atomicAdd(&g_cnt1[b], 1);
        slast = (old == NCHUNK - 1);
        if (slast) g_cnt1[b] = 0;           // reset for next graph replay
    }
    __syncthreads();
    if (!slast) return;

    // =================== k2 tail for batch b ===================
    const int t = tid;

    float wreg[32];
#pragma unroll
    for (int j = 0; j < 32; j++) wreg[j] = g_w[b * SS + j * 256 + t];

    __shared__ float sredf[8];
    __shared__ float sZ;
    __shared__ int   stot[32];
    if (t < 32) stot[t] = 0;

    float z = 0.f;
#pragma unroll
    for (int j = 0; j < 32; j++) z += wreg[j];
#pragma unroll
    for (int off = 16; off; off >>= 1) z += __shfl_xor_sync(0xffffffffu, z, off);
    if (lane == 0) sredf[warp] = z;
    __syncthreads();
    if (t == 0) {
        float zz = 0.f;
        for (int i = 0; i < 8; i++) zz += sredf[i];
        sZ = zz;
    }

    // P chunk-reduction folded in
    {
        float p = 0.f;
#pragma unroll
        for (int c = 0; c < NCHUNK; c++)
            p += g_Ppart[((size_t)c * BB + b) * DD + t];
        g_Psum[b * DD + t] = p;
    }
    __syncthreads();
    const float invZ = 1.f / sZ;

    // exact KSEL-th largest via binary search on float bit patterns
    unsigned lo = 0x3E800000u;  // 0.25f
    unsigned hi = 0x40800000u;  // 4.0f
    int it = 0;
    while (hi - lo > 1u) {
        const unsigned mid = lo + ((hi - lo) >> 1);
        const float fm = __uint_as_float(mid);
        int c = 0;
#pragma unroll
        for (int j = 0; j < 32; j++) c += (wreg[j] >= fm);
        c = __reduce_add_sync(0xffffffffu, c);
        if (lane == 0) atomicAdd(&stot[it], c);
        __syncthreads();
        if (stot[it] >= KSEL) lo = mid; else hi = mid;
        it++;
    }
    const float thr = __uint_as_float(lo);
    if (t == 0) g_invZ[b] = invZ;

    unsigned accmask = 0u;
    int cnt = 0;
#pragma unroll
    for (int j = 0; j < 32; j++) {
        const float wv = wreg[j];
        const bool a = (wv >= thr);
        accmask |= (a ? 1u : 0u) << j;
        cnt += a ? 1 : 0;
        out_a[b * SS + j * 256 + t] = wv * invZ * (a ? 1.5f : 1.0f);
    }

    // deterministic ordered compaction of accepted indices
    int v2 = cnt;
#pragma unroll
    for (int off = 1; off < 32; off <<= 1) {
        const int n = __shfl_up_sync(0xffffffffu, v2, off);
        if (lane >= off) v2 += n;
    }
    __shared__ int swsum[8];
    __shared__ int swbase[8];
    if (lane == 31) swsum[warp] = v2;
    __syncthreads();
    if (t == 0) {
        int s = 0;
        for (int i = 0; i < 8; i++) { swbase[i] = s; s += swsum[i]; }
        g_cntE[b] = s;
    }
    __syncthreads();
    int base = swbase[warp] + v2 - cnt;
    int* dst = g_idx + b * SS;
#pragma unroll
    for (int j = 0; j < 32; j++) {
        if ((accmask >> j) & 1u) dst[base++] = j * 256 + t;
    }
}

// ---------------------------------------------------------------------------
// kB: dense gather over compacted index list — fully branchless inner body
// (invalid slots clamp to row 0 with weight 0) so all gather LDGs batch.
// Grid: BB*ECHUNK = 512 blocks x 256 threads; warp g in 0..127 per batch
// handles slots g, g+128, ... Tail = final combine.
// ---------------------------------------------------------------------------
__global__ __launch_bounds__(256) void kB_kernel(const float* __restrict__ x,
                                                 float* __restrict__ out_sum)
{
    const int b     = blockIdx.x / ECHUNK;
    const int chunk = blockIdx.x % ECHUNK;
    const int warp  = threadIdx.x >> 5;
    const int lane  = threadIdx.x & 31;
    const int g     = chunk * 8 + warp;   // 0..127

    const int cnt = g_cntE[b];
    const int*   idx  = g_idx + b * SS;
    const float* wrow = g_w + b * SS;
    const float4* xb  = (const float4*)(x + (size_t)b * SS * DD);

    float acc[8];
#pragma unroll
    for (int j = 0; j < 8; j++) acc[j] = 0.f;

    for (int sbase = g; sbase < cnt; sbase += 8 * 128) {
        int   rr[8];
        float ww[8];
#pragma unroll
        for (int k = 0; k < 8; k++) {
            const int s = sbase + k * 128;
            const bool vld = (s < cnt);
            const int r2 = vld ? idx[s] : 0;      // clamp: safe row 0
            rr[k] = r2;
            ww[k] = vld ? wrow[r2] : 0.f;         // weight 0 nullifies
        }
#pragma unroll
        for (int k = 0; k < 8; k++) {             // branchless: LDGs batch
            const float4* x0 = xb + (size_t)rr[k] * (DD / 4);
            const float4 a0 = x0[lane];
            const float4 a1 = x0[32 + lane];
            const float w0 = ww[k];
            acc[0] += a0.x * w0; acc[1] += a0.y * w0;
            acc[2] += a0.z * w0; acc[3] += a0.w * w0;
            acc[4] += a1.x * w0; acc[5] += a1.y * w0;
            acc[6] += a1.z * w0; acc[7] += a1.w * w0;
        }
    }

    __shared__ float sacc[8][DD];
#pragma unroll
    for (int j = 0; j < 4; j++) {
        sacc[warp][lane * 4 + j]       = acc[j];
        sacc[warp][128 + lane * 4 + j] = acc[4 + j];
    }
    __syncthreads();
    {
        float tot = 0.f;
#pragma unroll
        for (int wp = 0; wp < 8; wp++) tot += sacc[wp][threadIdx.x];
        g_Epart[((size_t)chunk * BB + b) * DD + threadIdx.x] = tot;
    }

    // ---- last-block-per-batch gate ----
    __threadfence();
    __shared__ int slast;
    if (threadIdx.x == 0) {
        const int old = atomicAdd(&g_cnt2[b], 1);
        slast = (old == ECHUNK - 1);
        if (slast) g_cnt2[b] = 0;
    }
    __syncthreads();
    if (!slast) return;

    // =================== final combine for batch b ===================
    const int t = threadIdx.x;
    float esum = 0.f;
#pragma unroll
    for (int c = 0; c < ECHUNK; c++)
        esum += g_Epart[((size_t)c * BB + b) * DD + t];
    out_sum[b * DD + t] = g_invZ[b] * (g_Psum[b * DD + t] + 0.5f * esum);
}

// ---------------------------------------------------------------------------
extern "C" void kernel_launch(void* const* d_in, const int* in_sizes, int n_in,
                              void* d_out, int out_size)
{
    const float* x    = (const float*)d_in[0];
    const float* W    = (const float*)d_in[1];
    const float* bias = (const float*)d_in[2];

    float* out      = (float*)d_out;
    float* out_sum  = out;              // [BB, DD]
    float* out_a    = out + BB * DD;    // [BB, SS]

    cudaFuncSetAttribute(kA_kernel,
                         cudaFuncAttributeMaxDynamicSharedMemorySize, KA_SMEM);

    kA_kernel<<<BB * NCHUNK, 256, KA_SMEM>>>(x, W, bias, out_a);
    kB_kernel<<<BB * ECHUNK, 256>>>(x, out_sum);
}